// round 1
// baseline (speedup 1.0000x reference)
#include <cuda_runtime.h>
#include <cstdint>
#include <cstddef>

#define BATCH 32
#define C_CH  2048
#define N_SP  1152   // 48*24
#define MIDC  128

// ---------------- scratch (device globals; no allocation allowed) ----------------
__device__ __align__(128) float g_q[(size_t)BATCH * N_SP * MIDC];     // [b][n][m]
__device__ __align__(128) float g_k[(size_t)BATCH * MIDC * N_SP];     // [b][m][n]
__device__ __align__(128) float g_attn[(size_t)BATCH * N_SP * N_SP];  // [b][i][j]

// ---------------- helpers ----------------
__device__ __forceinline__ uint32_t f32_to_tf32(float x) {
    uint32_t r;
    asm("cvt.rna.tf32.f32 %0, %1;" : "=r"(r) : "f"(x));
    return r;
}

__device__ __forceinline__ void cp_async16(void* smem, const void* gmem) {
    uint32_t s = (uint32_t)__cvta_generic_to_shared(smem);
    asm volatile("cp.async.cg.shared.global [%0], [%1], 16;" :: "r"(s), "l"(gmem));
}
__device__ __forceinline__ void cp_commit() {
    asm volatile("cp.async.commit_group;" ::: "memory");
}
template <int NN>
__device__ __forceinline__ void cp_wait() {
    asm volatile("cp.async.wait_group %0;" :: "n"(NN) : "memory");
}

__device__ __forceinline__ void mma_tf32(float c[4], const uint32_t a[4], const uint32_t b[2]) {
    asm volatile(
        "mma.sync.aligned.m16n8k8.row.col.f32.tf32.tf32.f32 "
        "{%0,%1,%2,%3}, {%4,%5,%6,%7}, {%8,%9}, {%0,%1,%2,%3};"
        : "+f"(c[0]), "+f"(c[1]), "+f"(c[2]), "+f"(c[3])
        : "r"(a[0]), "r"(a[1]), "r"(a[2]), "r"(a[3]), "r"(b[0]), "r"(b[1]));
}

// ============================================================================
// K1: fused projections. Per batch: Wsel[128,2048] @ x[2048,1152].
//   blockIdx.y = 0 -> q (store transposed: q[b][n][m])
//   blockIdx.y = 1 -> k (store k[b][m][n])
// fp32 (precision-critical: feeds exp()).
// ============================================================================
__global__ __launch_bounds__(256, 2) void k1_proj(
    const float* __restrict__ feat,
    const float* __restrict__ Wq,
    const float* __restrict__ Wk)
{
    const int nblk = blockIdx.x;          // 0..8
    const int mblk = blockIdx.y;          // 0..1
    const int b    = blockIdx.z;
    const float* W = (mblk == 0) ? Wq : Wk;
    const float* x = feat + (size_t)b * C_CH * N_SP;

    __shared__ float As[16][132];  // [k][m] (transposed on store)
    __shared__ float Bs[16][132];  // [k][n]

    const int tid = threadIdx.x;
    const int tx = tid & 15, ty = tid >> 4;
    const int n0 = nblk * 128;

    float acc[8][8] = {};

    for (int k0 = 0; k0 < C_CH; k0 += 16) {
        // A: W[row][k0 + c4*4 ..], 128 rows x 16 cols, stored transposed
        #pragma unroll
        for (int it = 0; it < 2; it++) {
            int id  = tid + it * 256;
            int row = id >> 2;
            int c4  = (id & 3) * 4;
            float4 v = *(const float4*)(W + (size_t)row * C_CH + k0 + c4);
            As[c4 + 0][row] = v.x; As[c4 + 1][row] = v.y;
            As[c4 + 2][row] = v.z; As[c4 + 3][row] = v.w;
        }
        // B: x[k0+row][n0 + c4*4 ..], 16 rows x 128 cols
        #pragma unroll
        for (int it = 0; it < 2; it++) {
            int id  = tid + it * 256;
            int row = id >> 5;
            int c4  = (id & 31) * 4;
            *(float4*)&Bs[row][c4] = *(const float4*)(x + (size_t)(k0 + row) * N_SP + n0 + c4);
        }
        __syncthreads();
        #pragma unroll
        for (int kk = 0; kk < 16; kk++) {
            float a[8], bb[8];
            *(float4*)&a[0]  = *(float4*)&As[kk][ty * 4];
            *(float4*)&a[4]  = *(float4*)&As[kk][ty * 4 + 64];
            *(float4*)&bb[0] = *(float4*)&Bs[kk][tx * 4];
            *(float4*)&bb[4] = *(float4*)&Bs[kk][tx * 4 + 64];
            #pragma unroll
            for (int i = 0; i < 8; i++)
                #pragma unroll
                for (int j = 0; j < 8; j++)
                    acc[i][j] = fmaf(a[i], bb[j], acc[i][j]);
        }
        __syncthreads();
    }

    if (mblk == 0) {
        float* q = g_q + (size_t)b * N_SP * MIDC;
        #pragma unroll
        for (int i = 0; i < 8; i++) {
            int m = ty * 4 + (i & 3) + (i >> 2) * 64;
            #pragma unroll
            for (int j = 0; j < 8; j++) {
                int n = n0 + tx * 4 + (j & 3) + (j >> 2) * 64;
                q[(size_t)n * MIDC + m] = acc[i][j];
            }
        }
    } else {
        float* kp = g_k + (size_t)b * MIDC * N_SP;
        #pragma unroll
        for (int i = 0; i < 8; i++) {
            int m = ty * 4 + (i & 3) + (i >> 2) * 64;
            #pragma unroll
            for (int j = 0; j < 8; j++) {
                int n = n0 + tx * 4 + (j & 3) + (j >> 2) * 64;
                kp[(size_t)m * N_SP + n] = acc[i][j];
            }
        }
    }
}

// ============================================================================
// K2a: logits L[b][i][j] = sum_m q[b][i][m] * k[b][m][j].  M=N=1152, K=128. fp32.
// ============================================================================
__global__ __launch_bounds__(256, 2) void k2_logits()
{
    const int jblk = blockIdx.x;   // 0..8
    const int iblk = blockIdx.y;   // 0..8
    const int b    = blockIdx.z;
    const float* A = g_q + (size_t)b * N_SP * MIDC;    // [1152][128]
    const float* B = g_k + (size_t)b * MIDC * N_SP;    // [128][1152]
    float* L = g_attn + (size_t)b * N_SP * N_SP;

    __shared__ float As[16][132];  // [k][i]
    __shared__ float Bs[16][132];  // [k][j]

    const int tid = threadIdx.x;
    const int tx = tid & 15, ty = tid >> 4;
    const int i0 = iblk * 128, j0 = jblk * 128;

    float acc[8][8] = {};

    for (int k0 = 0; k0 < MIDC; k0 += 16) {
        #pragma unroll
        for (int it = 0; it < 2; it++) {
            int id  = tid + it * 256;
            int row = id >> 2;
            int c4  = (id & 3) * 4;
            float4 v = *(const float4*)(A + (size_t)(i0 + row) * MIDC + k0 + c4);
            As[c4 + 0][row] = v.x; As[c4 + 1][row] = v.y;
            As[c4 + 2][row] = v.z; As[c4 + 3][row] = v.w;
        }
        #pragma unroll
        for (int it = 0; it < 2; it++) {
            int id  = tid + it * 256;
            int row = id >> 5;
            int c4  = (id & 31) * 4;
            *(float4*)&Bs[row][c4] = *(const float4*)(B + (size_t)(k0 + row) * N_SP + j0 + c4);
        }
        __syncthreads();
        #pragma unroll
        for (int kk = 0; kk < 16; kk++) {
            float a[8], bb[8];
            *(float4*)&a[0]  = *(float4*)&As[kk][ty * 4];
            *(float4*)&a[4]  = *(float4*)&As[kk][ty * 4 + 64];
            *(float4*)&bb[0] = *(float4*)&Bs[kk][tx * 4];
            *(float4*)&bb[4] = *(float4*)&Bs[kk][tx * 4 + 64];
            #pragma unroll
            for (int i = 0; i < 8; i++)
                #pragma unroll
                for (int j = 0; j < 8; j++)
                    acc[i][j] = fmaf(a[i], bb[j], acc[i][j]);
        }
        __syncthreads();
    }

    #pragma unroll
    for (int i = 0; i < 8; i++) {
        int ii = i0 + ty * 4 + (i & 3) + (i >> 2) * 64;
        #pragma unroll
        for (int j = 0; j < 8; j++) {
            int jj = j0 + tx * 4 + (j & 3) + (j >> 2) * 64;
            L[(size_t)ii * N_SP + jj] = acc[i][j];
        }
    }
}

// ============================================================================
// K2b: row softmax over g_attn rows (length 1152), one warp per row.
// Output rounded to tf32 (RNA) so K3 can consume directly.
// ============================================================================
__global__ void k2_softmax()
{
    const int row  = blockIdx.x * 8 + (threadIdx.x >> 5);  // [0, 32*1152)
    const int lane = threadIdx.x & 31;
    float* r = g_attn + (size_t)row * N_SP;

    float f[36];
    float mx = -1e30f;
    #pragma unroll
    for (int t = 0; t < 36; t++) {
        f[t] = r[lane + 32 * t];
        mx = fmaxf(mx, f[t]);
    }
    #pragma unroll
    for (int o = 16; o > 0; o >>= 1) mx = fmaxf(mx, __shfl_xor_sync(0xffffffffu, mx, o));

    float s = 0.0f;
    #pragma unroll
    for (int t = 0; t < 36; t++) {
        f[t] = __expf(f[t] - mx);
        s += f[t];
    }
    #pragma unroll
    for (int o = 16; o > 0; o >>= 1) s += __shfl_xor_sync(0xffffffffu, s, o);

    const float inv = 1.0f / s;
    #pragma unroll
    for (int t = 0; t < 36; t++)
        r[lane + 32 * t] = __uint_as_float(f32_to_tf32(f[t] * inv));
}

// ============================================================================
// K3: refined = cam[b] @ attn[b]; out = alpha*refined + cam.
// TF32 mma.sync m16n8k8, 128x128 block tile, 2(m)x4(n) warps of 64x32,
// BK=16, 2-stage cp.async pipeline.
// ============================================================================
__global__ __launch_bounds__(256, 2) void k3_refined(
    const float* __restrict__ cam,
    const float* __restrict__ alphaPtr,
    float* __restrict__ out)
{
    const int jblk = blockIdx.x;   // 0..8
    const int cblk = blockIdx.y;   // 0..15
    const int b    = blockIdx.z;

    const float* A  = cam   + (size_t)b * C_CH * N_SP;   // [2048][1152]
    const float* Bm = g_attn + (size_t)b * N_SP * N_SP;  // [1152][1152] (tf32-rounded)

    __shared__ float As[2][128][20];   // [m][k], pad 4
    __shared__ float Bs[2][16][132];   // [k][j], pad 4

    const int tid  = threadIdx.x;
    const int warp = tid >> 5, lane = tid & 31;
    const int wm = warp >> 2, wn = warp & 3;   // 2 x 4 warp grid
    const int g = lane >> 2, tig = lane & 3;
    const int c0 = cblk * 128, j0 = jblk * 128;

    float acc[4][4][4] = {};

    // --- stage loader ---
    auto loadStage = [&](int kt, int buf) {
        const int k0 = kt * 16;
        #pragma unroll
        for (int it = 0; it < 2; it++) {              // A: 128x16 = 512 float4
            int id  = tid + it * 256;
            int row = id >> 2;
            int c4  = (id & 3) * 4;
            cp_async16(&As[buf][row][c4], A + (size_t)(c0 + row) * N_SP + k0 + c4);
        }
        #pragma unroll
        for (int it = 0; it < 2; it++) {              // B: 16x128 = 512 float4
            int id  = tid + it * 256;
            int row = id >> 5;
            int c4  = (id & 31) * 4;
            cp_async16(&Bs[buf][row][c4], Bm + (size_t)(k0 + row) * N_SP + j0 + c4);
        }
    };

    loadStage(0, 0);
    cp_commit();

    const int KT = N_SP / 16;   // 72
    for (int kt = 0; kt < KT; kt++) {
        const int buf = kt & 1;
        if (kt + 1 < KT) {
            loadStage(kt + 1, (kt + 1) & 1);
            cp_commit();
            cp_wait<1>();
        } else {
            cp_wait<0>();
        }
        __syncthreads();

        #pragma unroll
        for (int ks = 0; ks < 2; ks++) {
            const int kb = ks * 8;
            uint32_t afr[4][4], bfr[4][2];
            #pragma unroll
            for (int fm = 0; fm < 4; fm++) {
                int mr = wm * 64 + fm * 16;
                afr[fm][0] = f32_to_tf32(As[buf][mr + g    ][kb + tig    ]);
                afr[fm][1] = f32_to_tf32(As[buf][mr + g + 8][kb + tig    ]);
                afr[fm][2] = f32_to_tf32(As[buf][mr + g    ][kb + tig + 4]);
                afr[fm][3] = f32_to_tf32(As[buf][mr + g + 8][kb + tig + 4]);
            }
            #pragma unroll
            for (int fn = 0; fn < 4; fn++) {
                int jc = wn * 32 + fn * 8;
                bfr[fn][0] = __float_as_uint(Bs[buf][kb + tig    ][jc + g]);
                bfr[fn][1] = __float_as_uint(Bs[buf][kb + tig + 4][jc + g]);
            }
            #pragma unroll
            for (int fm = 0; fm < 4; fm++)
                #pragma unroll
                for (int fn = 0; fn < 4; fn++)
                    mma_tf32(acc[fm][fn], afr[fm], bfr[fn]);
        }
        __syncthreads();
    }

    // --- epilogue: out = alpha*acc + cam ---
    const float alpha = alphaPtr[0];
    const size_t base = (size_t)b * C_CH * N_SP;
    #pragma unroll
    for (int fm = 0; fm < 4; fm++) {
        #pragma unroll
        for (int fn = 0; fn < 4; fn++) {
            int mrow = c0 + wm * 64 + fm * 16 + g;
            int col  = j0 + wn * 32 + fn * 8 + tig * 2;
            const float2 cv0 = *(const float2*)(A + (size_t)mrow * N_SP + col);
            const float2 cv1 = *(const float2*)(A + (size_t)(mrow + 8) * N_SP + col);
            float2 r0, r1;
            r0.x = fmaf(alpha, acc[fm][fn][0], cv0.x);
            r0.y = fmaf(alpha, acc[fm][fn][1], cv0.y);
            r1.x = fmaf(alpha, acc[fm][fn][2], cv1.x);
            r1.y = fmaf(alpha, acc[fm][fn][3], cv1.y);
            *(float2*)(out + base + (size_t)mrow * N_SP + col)       = r0;
            *(float2*)(out + base + (size_t)(mrow + 8) * N_SP + col) = r1;
        }
    }
}

// ============================================================================
extern "C" void kernel_launch(void* const* d_in, const int* in_sizes, int n_in,
                              void* d_out, int out_size)
{
    (void)in_sizes; (void)n_in; (void)out_size;
    const float* feat  = (const float*)d_in[0];
    const float* cam   = (const float*)d_in[1];
    const float* Wq    = (const float*)d_in[2];
    const float* Wk    = (const float*)d_in[3];
    const float* alpha = (const float*)d_in[4];
    float* out = (float*)d_out;

    k1_proj<<<dim3(9, 2, BATCH), 256>>>(feat, Wq, Wk);
    k2_logits<<<dim3(9, 9, BATCH), 256>>>();
    k2_softmax<<<(BATCH * N_SP) / 8, 256>>>();
    k3_refined<<<dim3(9, 16, BATCH), 256>>>(cam, alpha, out);
}

// round 2
// speedup vs baseline: 1.0996x; 1.0996x over previous
#include <cuda_runtime.h>
#include <cstdint>
#include <cstddef>

#define BATCH 32
#define C_CH  2048
#define N_SP  1152   // 48*24
#define MIDC  128

// ---------------- scratch (device globals; no allocation allowed) ----------------
__device__ __align__(128) float g_q[(size_t)BATCH * N_SP * MIDC];     // [b][n][m]
__device__ __align__(128) float g_k[(size_t)BATCH * MIDC * N_SP];     // [b][m][n]
__device__ __align__(128) float g_attn[(size_t)BATCH * N_SP * N_SP];  // [b][i][j]

// ---------------- helpers ----------------
__device__ __forceinline__ uint32_t f32_to_tf32(float x) {
    uint32_t r;
    asm("cvt.rna.tf32.f32 %0, %1;" : "=r"(r) : "f"(x));
    return r;
}
__device__ __forceinline__ void split_tf32(float x, uint32_t& hi, uint32_t& lo) {
    hi = f32_to_tf32(x);
    lo = f32_to_tf32(x - __uint_as_float(hi));
}

__device__ __forceinline__ void cp_async16(void* smem, const void* gmem) {
    uint32_t s = (uint32_t)__cvta_generic_to_shared(smem);
    asm volatile("cp.async.cg.shared.global [%0], [%1], 16;" :: "r"(s), "l"(gmem));
}
__device__ __forceinline__ void cp_commit() {
    asm volatile("cp.async.commit_group;" ::: "memory");
}
template <int NN>
__device__ __forceinline__ void cp_wait() {
    asm volatile("cp.async.wait_group %0;" :: "n"(NN) : "memory");
}

__device__ __forceinline__ void mma_tf32(float c[4], const uint32_t a[4], const uint32_t b[2]) {
    asm volatile(
        "mma.sync.aligned.m16n8k8.row.col.f32.tf32.tf32.f32 "
        "{%0,%1,%2,%3}, {%4,%5,%6,%7}, {%8,%9}, {%0,%1,%2,%3};"
        : "+f"(c[0]), "+f"(c[1]), "+f"(c[2]), "+f"(c[3])
        : "r"(a[0]), "r"(a[1]), "r"(a[2]), "r"(a[3]), "r"(b[0]), "r"(b[1]));
}

// Shared-memory stage geometry (same for all GEMMs):
//   As: 128 rows (m) x 16 cols (k), padded to 20 floats/row
//   Bs: 16 rows (k) x 128 cols (n), padded to 132 floats/row
#define AS_ELEMS (128 * 20)
#define BS_ELEMS (16 * 132)
#define STAGE_ELEMS (AS_ELEMS + BS_ELEMS)
#define NSTAGE 3
#define SMEM_BYTES (NSTAGE * STAGE_ELEMS * 4)

// ============================================================================
// K1: fused projections via 3xTF32 tensor cores.
// Per batch: Wsel[128,2048] @ x[2048,1152].
//   blockIdx.y = 0 -> q (store transposed: q[b][n][m])
//   blockIdx.y = 1 -> k (store k[b][m][n])
// ============================================================================
__global__ __launch_bounds__(256, 2) void k1_proj(
    const float* __restrict__ feat,
    const float* __restrict__ Wq,
    const float* __restrict__ Wk)
{
    const int nblk = blockIdx.x;          // 0..8
    const int mblk = blockIdx.y;          // 0..1
    const int b    = blockIdx.z;
    const float* W = (mblk == 0) ? Wq : Wk;
    const float* X = feat + (size_t)b * C_CH * N_SP;

    extern __shared__ float smem[];
    float (*As)[128][20]  = (float(*)[128][20])smem;
    float (*Bs)[16][132]  = (float(*)[16][132])(smem + NSTAGE * AS_ELEMS);

    const int tid  = threadIdx.x;
    const int warp = tid >> 5, lane = tid & 31;
    const int wm = warp >> 2, wn = warp & 3;
    const int g = lane >> 2, tig = lane & 3;
    const int n0 = nblk * 128;

    float acc[4][4][4] = {};

    auto loadStage = [&](int kt, int buf) {
        const int k0 = kt * 16;
        #pragma unroll
        for (int it = 0; it < 2; it++) {          // A: 128x16
            int id  = tid + it * 256;
            int row = id >> 2;
            int c4  = (id & 3) * 4;
            cp_async16(&As[buf][row][c4], W + (size_t)row * C_CH + k0 + c4);
        }
        #pragma unroll
        for (int it = 0; it < 2; it++) {          // B: 16x128
            int id  = tid + it * 256;
            int row = id >> 5;
            int c4  = (id & 31) * 4;
            cp_async16(&Bs[buf][row][c4], X + (size_t)(k0 + row) * N_SP + n0 + c4);
        }
    };

    const int KT = C_CH / 16;   // 128
    loadStage(0, 0); cp_commit();
    loadStage(1, 1); cp_commit();

    for (int kt = 0; kt < KT; kt++) {
        if (kt + 1 < KT) cp_wait<1>(); else cp_wait<0>();
        __syncthreads();
        const int buf = kt % 3;
        if (kt + 2 < KT) { loadStage(kt + 2, (kt + 2) % 3); cp_commit(); }

        #pragma unroll
        for (int ks = 0; ks < 2; ks++) {
            const int kb = ks * 8;
            uint32_t bhi[4][2], blo[4][2];
            #pragma unroll
            for (int fn = 0; fn < 4; fn++) {
                int jc = wn * 32 + fn * 8;
                split_tf32(Bs[buf][kb + tig    ][jc + g], bhi[fn][0], blo[fn][0]);
                split_tf32(Bs[buf][kb + tig + 4][jc + g], bhi[fn][1], blo[fn][1]);
            }
            #pragma unroll
            for (int fm = 0; fm < 4; fm++) {
                int mr = wm * 64 + fm * 16;
                uint32_t ahi[4], alo[4];
                split_tf32(As[buf][mr + g    ][kb + tig    ], ahi[0], alo[0]);
                split_tf32(As[buf][mr + g + 8][kb + tig    ], ahi[1], alo[1]);
                split_tf32(As[buf][mr + g    ][kb + tig + 4], ahi[2], alo[2]);
                split_tf32(As[buf][mr + g + 8][kb + tig + 4], ahi[3], alo[3]);
                #pragma unroll
                for (int fn = 0; fn < 4; fn++) {
                    mma_tf32(acc[fm][fn], ahi, bhi[fn]);
                    mma_tf32(acc[fm][fn], alo, bhi[fn]);
                    mma_tf32(acc[fm][fn], ahi, blo[fn]);
                }
            }
        }
    }

    if (mblk == 0) {
        float* q = g_q + (size_t)b * N_SP * MIDC;
        #pragma unroll
        for (int fm = 0; fm < 4; fm++) {
            #pragma unroll
            for (int fn = 0; fn < 4; fn++) {
                int m   = wm * 64 + fm * 16 + g;
                int col = n0 + wn * 32 + fn * 8 + tig * 2;
                q[(size_t)(col    ) * MIDC + m    ] = acc[fm][fn][0];
                q[(size_t)(col + 1) * MIDC + m    ] = acc[fm][fn][1];
                q[(size_t)(col    ) * MIDC + m + 8] = acc[fm][fn][2];
                q[(size_t)(col + 1) * MIDC + m + 8] = acc[fm][fn][3];
            }
        }
    } else {
        float* kp = g_k + (size_t)b * MIDC * N_SP;
        #pragma unroll
        for (int fm = 0; fm < 4; fm++) {
            #pragma unroll
            for (int fn = 0; fn < 4; fn++) {
                int m   = wm * 64 + fm * 16 + g;
                int col = n0 + wn * 32 + fn * 8 + tig * 2;
                *(float2*)(kp + (size_t)m * N_SP + col)       = make_float2(acc[fm][fn][0], acc[fm][fn][1]);
                *(float2*)(kp + (size_t)(m + 8) * N_SP + col) = make_float2(acc[fm][fn][2], acc[fm][fn][3]);
            }
        }
    }
}

// ============================================================================
// K2a: logits L[b][i][j] = sum_m q[b][i][m] * k[b][m][j]. 3xTF32, K=128.
// ============================================================================
__global__ __launch_bounds__(256, 2) void k2_logits()
{
    const int jblk = blockIdx.x;   // 0..8
    const int iblk = blockIdx.y;   // 0..8
    const int b    = blockIdx.z;
    const float* A = g_q + (size_t)b * N_SP * MIDC;    // [1152][128]
    const float* B = g_k + (size_t)b * MIDC * N_SP;    // [128][1152]
    float* L = g_attn + (size_t)b * N_SP * N_SP;

    extern __shared__ float smem[];
    float (*As)[128][20] = (float(*)[128][20])smem;
    float (*Bs)[16][132] = (float(*)[16][132])(smem + NSTAGE * AS_ELEMS);

    const int tid  = threadIdx.x;
    const int warp = tid >> 5, lane = tid & 31;
    const int wm = warp >> 2, wn = warp & 3;
    const int g = lane >> 2, tig = lane & 3;
    const int i0 = iblk * 128, j0 = jblk * 128;

    float acc[4][4][4] = {};

    auto loadStage = [&](int kt, int buf) {
        const int k0 = kt * 16;
        #pragma unroll
        for (int it = 0; it < 2; it++) {
            int id  = tid + it * 256;
            int row = id >> 2;
            int c4  = (id & 3) * 4;
            cp_async16(&As[buf][row][c4], A + (size_t)(i0 + row) * MIDC + k0 + c4);
        }
        #pragma unroll
        for (int it = 0; it < 2; it++) {
            int id  = tid + it * 256;
            int row = id >> 5;
            int c4  = (id & 31) * 4;
            cp_async16(&Bs[buf][row][c4], B + (size_t)(k0 + row) * N_SP + j0 + c4);
        }
    };

    const int KT = MIDC / 16;   // 8
    loadStage(0, 0); cp_commit();
    loadStage(1, 1); cp_commit();

    for (int kt = 0; kt < KT; kt++) {
        if (kt + 1 < KT) cp_wait<1>(); else cp_wait<0>();
        __syncthreads();
        const int buf = kt % 3;
        if (kt + 2 < KT) { loadStage(kt + 2, (kt + 2) % 3); cp_commit(); }

        #pragma unroll
        for (int ks = 0; ks < 2; ks++) {
            const int kb = ks * 8;
            uint32_t bhi[4][2], blo[4][2];
            #pragma unroll
            for (int fn = 0; fn < 4; fn++) {
                int jc = wn * 32 + fn * 8;
                split_tf32(Bs[buf][kb + tig    ][jc + g], bhi[fn][0], blo[fn][0]);
                split_tf32(Bs[buf][kb + tig + 4][jc + g], bhi[fn][1], blo[fn][1]);
            }
            #pragma unroll
            for (int fm = 0; fm < 4; fm++) {
                int mr = wm * 64 + fm * 16;
                uint32_t ahi[4], alo[4];
                split_tf32(As[buf][mr + g    ][kb + tig    ], ahi[0], alo[0]);
                split_tf32(As[buf][mr + g + 8][kb + tig    ], ahi[1], alo[1]);
                split_tf32(As[buf][mr + g    ][kb + tig + 4], ahi[2], alo[2]);
                split_tf32(As[buf][mr + g + 8][kb + tig + 4], ahi[3], alo[3]);
                #pragma unroll
                for (int fn = 0; fn < 4; fn++) {
                    mma_tf32(acc[fm][fn], ahi, bhi[fn]);
                    mma_tf32(acc[fm][fn], alo, bhi[fn]);
                    mma_tf32(acc[fm][fn], ahi, blo[fn]);
                }
            }
        }
    }

    #pragma unroll
    for (int fm = 0; fm < 4; fm++) {
        #pragma unroll
        for (int fn = 0; fn < 4; fn++) {
            int ii  = i0 + wm * 64 + fm * 16 + g;
            int col = j0 + wn * 32 + fn * 8 + tig * 2;
            *(float2*)(L + (size_t)ii * N_SP + col)       = make_float2(acc[fm][fn][0], acc[fm][fn][1]);
            *(float2*)(L + (size_t)(ii + 8) * N_SP + col) = make_float2(acc[fm][fn][2], acc[fm][fn][3]);
        }
    }
}

// ============================================================================
// K2b: row softmax (length 1152), one warp per row. Output tf32-rounded.
// ============================================================================
__global__ void k2_softmax()
{
    const int row  = blockIdx.x * 8 + (threadIdx.x >> 5);
    const int lane = threadIdx.x & 31;
    float* r = g_attn + (size_t)row * N_SP;

    float f[36];
    float mx = -1e30f;
    #pragma unroll
    for (int t = 0; t < 36; t++) {
        f[t] = r[lane + 32 * t];
        mx = fmaxf(mx, f[t]);
    }
    #pragma unroll
    for (int o = 16; o > 0; o >>= 1) mx = fmaxf(mx, __shfl_xor_sync(0xffffffffu, mx, o));

    float s = 0.0f;
    #pragma unroll
    for (int t = 0; t < 36; t++) {
        f[t] = __expf(f[t] - mx);
        s += f[t];
    }
    #pragma unroll
    for (int o = 16; o > 0; o >>= 1) s += __shfl_xor_sync(0xffffffffu, s, o);

    const float inv = 1.0f / s;
    #pragma unroll
    for (int t = 0; t < 36; t++)
        r[lane + 32 * t] = __uint_as_float(f32_to_tf32(f[t] * inv));
}

// ============================================================================
// K3: refined = cam[b] @ attn[b]; out = alpha*refined + cam.
// Single-pass TF32 (attn pre-rounded; cam rounded per-fragment). 3-stage pipeline.
// ============================================================================
__global__ __launch_bounds__(256, 2) void k3_refined(
    const float* __restrict__ cam,
    const float* __restrict__ alphaPtr,
    float* __restrict__ out)
{
    const int jblk = blockIdx.x;   // 0..8
    const int cblk = blockIdx.y;   // 0..15
    const int b    = blockIdx.z;

    const float* A  = cam    + (size_t)b * C_CH * N_SP;   // [2048][1152]
    const float* Bm = g_attn + (size_t)b * N_SP * N_SP;   // [1152][1152] tf32-rounded

    extern __shared__ float smem[];
    float (*As)[128][20] = (float(*)[128][20])smem;
    float (*Bs)[16][132] = (float(*)[16][132])(smem + NSTAGE * AS_ELEMS);

    const int tid  = threadIdx.x;
    const int warp = tid >> 5, lane = tid & 31;
    const int wm = warp >> 2, wn = warp & 3;
    const int g = lane >> 2, tig = lane & 3;
    const int c0 = cblk * 128, j0 = jblk * 128;

    float acc[4][4][4] = {};

    auto loadStage = [&](int kt, int buf) {
        const int k0 = kt * 16;
        #pragma unroll
        for (int it = 0; it < 2; it++) {
            int id  = tid + it * 256;
            int row = id >> 2;
            int c4  = (id & 3) * 4;
            cp_async16(&As[buf][row][c4], A + (size_t)(c0 + row) * N_SP + k0 + c4);
        }
        #pragma unroll
        for (int it = 0; it < 2; it++) {
            int id  = tid + it * 256;
            int row = id >> 5;
            int c4  = (id & 31) * 4;
            cp_async16(&Bs[buf][row][c4], Bm + (size_t)(k0 + row) * N_SP + j0 + c4);
        }
    };

    const int KT = N_SP / 16;   // 72
    loadStage(0, 0); cp_commit();
    loadStage(1, 1); cp_commit();

    for (int kt = 0; kt < KT; kt++) {
        if (kt + 1 < KT) cp_wait<1>(); else cp_wait<0>();
        __syncthreads();
        const int buf = kt % 3;
        if (kt + 2 < KT) { loadStage(kt + 2, (kt + 2) % 3); cp_commit(); }

        #pragma unroll
        for (int ks = 0; ks < 2; ks++) {
            const int kb = ks * 8;
            uint32_t bfr[4][2];
            #pragma unroll
            for (int fn = 0; fn < 4; fn++) {
                int jc = wn * 32 + fn * 8;
                bfr[fn][0] = __float_as_uint(Bs[buf][kb + tig    ][jc + g]);
                bfr[fn][1] = __float_as_uint(Bs[buf][kb + tig + 4][jc + g]);
            }
            #pragma unroll
            for (int fm = 0; fm < 4; fm++) {
                int mr = wm * 64 + fm * 16;
                uint32_t afr[4];
                afr[0] = f32_to_tf32(As[buf][mr + g    ][kb + tig    ]);
                afr[1] = f32_to_tf32(As[buf][mr + g + 8][kb + tig    ]);
                afr[2] = f32_to_tf32(As[buf][mr + g    ][kb + tig + 4]);
                afr[3] = f32_to_tf32(As[buf][mr + g + 8][kb + tig + 4]);
                #pragma unroll
                for (int fn = 0; fn < 4; fn++)
                    mma_tf32(acc[fm][fn], afr, bfr[fn]);
            }
        }
    }

    const float alpha = alphaPtr[0];
    const size_t base = (size_t)b * C_CH * N_SP;
    #pragma unroll
    for (int fm = 0; fm < 4; fm++) {
        #pragma unroll
        for (int fn = 0; fn < 4; fn++) {
            int mrow = c0 + wm * 64 + fm * 16 + g;
            int col  = j0 + wn * 32 + fn * 8 + tig * 2;
            const float2 cv0 = *(const float2*)(A + (size_t)mrow * N_SP + col);
            const float2 cv1 = *(const float2*)(A + (size_t)(mrow + 8) * N_SP + col);
            float2 r0, r1;
            r0.x = fmaf(alpha, acc[fm][fn][0], cv0.x);
            r0.y = fmaf(alpha, acc[fm][fn][1], cv0.y);
            r1.x = fmaf(alpha, acc[fm][fn][2], cv1.x);
            r1.y = fmaf(alpha, acc[fm][fn][3], cv1.y);
            *(float2*)(out + base + (size_t)mrow * N_SP + col)       = r0;
            *(float2*)(out + base + (size_t)(mrow + 8) * N_SP + col) = r1;
        }
    }
}

// ============================================================================
extern "C" void kernel_launch(void* const* d_in, const int* in_sizes, int n_in,
                              void* d_out, int out_size)
{
    (void)in_sizes; (void)n_in; (void)out_size;
    const float* feat  = (const float*)d_in[0];
    const float* cam   = (const float*)d_in[1];
    const float* Wq    = (const float*)d_in[2];
    const float* Wk    = (const float*)d_in[3];
    const float* alpha = (const float*)d_in[4];
    float* out = (float*)d_out;

    cudaFuncSetAttribute(k1_proj,    cudaFuncAttributeMaxDynamicSharedMemorySize, SMEM_BYTES);
    cudaFuncSetAttribute(k2_logits,  cudaFuncAttributeMaxDynamicSharedMemorySize, SMEM_BYTES);
    cudaFuncSetAttribute(k3_refined, cudaFuncAttributeMaxDynamicSharedMemorySize, SMEM_BYTES);

    k1_proj<<<dim3(9, 2, BATCH), 256, SMEM_BYTES>>>(feat, Wq, Wk);
    k2_logits<<<dim3(9, 9, BATCH), 256, SMEM_BYTES>>>();
    k2_softmax<<<(BATCH * N_SP) / 8, 256>>>();
    k3_refined<<<dim3(9, 16, BATCH), 256, SMEM_BYTES>>>(cam, alpha, out);
}

// round 4
// speedup vs baseline: 1.2298x; 1.1184x over previous
#include <cuda_runtime.h>
#include <cstdint>
#include <cstddef>

#define BATCH 32
#define C_CH  2048
#define N_SP  1152   // 48*24
#define MIDC  128

// ---------------- scratch (device globals; no allocation allowed) ----------------
__device__ __align__(128) float g_q[(size_t)BATCH * N_SP * MIDC];     // [b][n][m]
__device__ __align__(128) float g_k[(size_t)BATCH * MIDC * N_SP];     // [b][m][n]
__device__ __align__(128) float g_attn[(size_t)BATCH * N_SP * N_SP];  // [b][i][j]
__device__ __align__(128) float g_Whi[2][(size_t)MIDC * C_CH];        // tf32 hi of Wq/Wk
__device__ __align__(128) float g_Wlo[2][(size_t)MIDC * C_CH];        // tf32 lo

// ---------------- helpers ----------------
__device__ __forceinline__ uint32_t f32_to_tf32(float x) {
    uint32_t r;
    asm("cvt.rna.tf32.f32 %0, %1;" : "=r"(r) : "f"(x));
    return r;
}
__device__ __forceinline__ void split_tf32(float x, uint32_t& hi, uint32_t& lo) {
    hi = f32_to_tf32(x);
    lo = f32_to_tf32(x - __uint_as_float(hi));
}
__device__ __forceinline__ void cp_async16(void* smem, const void* gmem) {
    uint32_t s = (uint32_t)__cvta_generic_to_shared(smem);
    asm volatile("cp.async.cg.shared.global [%0], [%1], 16;" :: "r"(s), "l"(gmem));
}
__device__ __forceinline__ void cp_commit() {
    asm volatile("cp.async.commit_group;" ::: "memory");
}
template <int NN>
__device__ __forceinline__ void cp_wait() {
    asm volatile("cp.async.wait_group %0;" :: "n"(NN) : "memory");
}
__device__ __forceinline__ void mma_tf32(float c[4], const uint32_t a[4], const uint32_t b[2]) {
    asm volatile(
        "mma.sync.aligned.m16n8k8.row.col.f32.tf32.tf32.f32 "
        "{%0,%1,%2,%3}, {%4,%5,%6,%7}, {%8,%9}, {%0,%1,%2,%3};"
        : "+f"(c[0]), "+f"(c[1]), "+f"(c[2]), "+f"(c[3])
        : "r"(a[0]), "r"(a[1]), "r"(a[2]), "r"(a[3]), "r"(b[0]), "r"(b[1]));
}

// ---- shared geometry ----
#define AS_ELEMS (128 * 20)
#define BS_ELEMS (16 * 132)
#define NSTAGE 3
#define K1_SMEM (NSTAGE * (2 * AS_ELEMS + BS_ELEMS) * 4)
#define K2_SMEM (NSTAGE * (AS_ELEMS + BS_ELEMS) * 4)
// K3 uses Bs pad 136 (conflict-free for its access pattern)
#define BS3_ELEMS (16 * 136)
#define K3_SMEM (NSTAGE * (AS_ELEMS + BS3_ELEMS) * 4)

// ============================================================================
// K0: one-time tf32 split of Wq/Wk (tiny).
// ============================================================================
__global__ void k0_splitW(const float* __restrict__ Wq, const float* __restrict__ Wk)
{
    const int i = blockIdx.x * 256 + threadIdx.x;
    if (i >= MIDC * C_CH) return;
    uint32_t h, l;
    split_tf32(Wq[i], h, l);
    g_Whi[0][i] = __uint_as_float(h); g_Wlo[0][i] = __uint_as_float(l);
    split_tf32(Wk[i], h, l);
    g_Whi[1][i] = __uint_as_float(h); g_Wlo[1][i] = __uint_as_float(l);
}

// ============================================================================
// K1: projections via 3xTF32 mma.sync. Wsel[128,2048] @ x[2048,1152].
//   mblk=0 -> q stored transposed g_q[b][n][m];  mblk=1 -> k stored g_k[b][m][n]
// A-side (W) pre-split by k0 (hi/lo tiles via cp.async, no in-loop split).
// ============================================================================
__global__ __launch_bounds__(256, 2) void k1_proj(const float* __restrict__ feat)
{
    const int nblk = blockIdx.x;          // 0..8
    const int mblk = blockIdx.y;          // 0..1
    const int b    = blockIdx.z;
    const float* Whi = g_Whi[mblk];
    const float* Wlo = g_Wlo[mblk];
    const float* X = feat + (size_t)b * C_CH * N_SP;

    extern __shared__ float smem[];
    float (*Ah)[128][20] = (float(*)[128][20])smem;
    float (*Al)[128][20] = (float(*)[128][20])(smem + NSTAGE * AS_ELEMS);
    float (*Bs)[16][132] = (float(*)[16][132])(smem + 2 * NSTAGE * AS_ELEMS);

    const int tid  = threadIdx.x;
    const int warp = tid >> 5, lane = tid & 31;
    const int wm = warp >> 2, wn = warp & 3;
    const int g = lane >> 2, tig = lane & 3;
    const int n0 = nblk * 128;

    float acc[4][4][4] = {};

    auto loadStage = [&](int kt, int buf) {
        const int k0 = kt * 16;
        #pragma unroll
        for (int it = 0; it < 2; it++) {          // A hi: 128x16
            int id  = tid + it * 256;
            int row = id >> 2;
            int c4  = (id & 3) * 4;
            cp_async16(&Ah[buf][row][c4], Whi + (size_t)row * C_CH + k0 + c4);
        }
        #pragma unroll
        for (int it = 0; it < 2; it++) {          // A lo
            int id  = tid + it * 256;
            int row = id >> 2;
            int c4  = (id & 3) * 4;
            cp_async16(&Al[buf][row][c4], Wlo + (size_t)row * C_CH + k0 + c4);
        }
        #pragma unroll
        for (int it = 0; it < 2; it++) {          // B: 16x128
            int id  = tid + it * 256;
            int row = id >> 5;
            int c4  = (id & 31) * 4;
            cp_async16(&Bs[buf][row][c4], X + (size_t)(k0 + row) * N_SP + n0 + c4);
        }
    };

    const int KT = C_CH / 16;   // 128
    loadStage(0, 0); cp_commit();
    loadStage(1, 1); cp_commit();

    for (int kt = 0; kt < KT; kt++) {
        if (kt + 1 < KT) cp_wait<1>(); else cp_wait<0>();
        __syncthreads();
        const int buf = kt % 3;
        if (kt + 2 < KT) { loadStage(kt + 2, (kt + 2) % 3); cp_commit(); }

        #pragma unroll
        for (int ks = 0; ks < 2; ks++) {
            const int kb = ks * 8;
            uint32_t bhi[4][2], blo[4][2];
            #pragma unroll
            for (int fn = 0; fn < 4; fn++) {
                int jc = wn * 32 + fn * 8;
                split_tf32(Bs[buf][kb + tig    ][jc + g], bhi[fn][0], blo[fn][0]);
                split_tf32(Bs[buf][kb + tig + 4][jc + g], bhi[fn][1], blo[fn][1]);
            }
            #pragma unroll
            for (int fm = 0; fm < 4; fm++) {
                int mr = wm * 64 + fm * 16;
                uint32_t ahi[4], alo[4];
                ahi[0] = __float_as_uint(Ah[buf][mr + g    ][kb + tig    ]);
                ahi[1] = __float_as_uint(Ah[buf][mr + g + 8][kb + tig    ]);
                ahi[2] = __float_as_uint(Ah[buf][mr + g    ][kb + tig + 4]);
                ahi[3] = __float_as_uint(Ah[buf][mr + g + 8][kb + tig + 4]);
                alo[0] = __float_as_uint(Al[buf][mr + g    ][kb + tig    ]);
                alo[1] = __float_as_uint(Al[buf][mr + g + 8][kb + tig    ]);
                alo[2] = __float_as_uint(Al[buf][mr + g    ][kb + tig + 4]);
                alo[3] = __float_as_uint(Al[buf][mr + g + 8][kb + tig + 4]);
                #pragma unroll
                for (int fn = 0; fn < 4; fn++) {
                    mma_tf32(acc[fm][fn], ahi, bhi[fn]);
                    mma_tf32(acc[fm][fn], alo, bhi[fn]);
                    mma_tf32(acc[fm][fn], ahi, blo[fn]);
                }
            }
        }
    }

    if (mblk == 0) {
        float* q = g_q + (size_t)b * N_SP * MIDC;   // [n][m]
        #pragma unroll
        for (int fm = 0; fm < 4; fm++) {
            #pragma unroll
            for (int fn = 0; fn < 4; fn++) {
                int m   = wm * 64 + fm * 16 + g;
                int col = n0 + wn * 32 + fn * 8 + tig * 2;
                q[(size_t)(col    ) * MIDC + m    ] = acc[fm][fn][0];
                q[(size_t)(col + 1) * MIDC + m    ] = acc[fm][fn][1];
                q[(size_t)(col    ) * MIDC + m + 8] = acc[fm][fn][2];
                q[(size_t)(col + 1) * MIDC + m + 8] = acc[fm][fn][3];
            }
        }
    } else {
        float* kp = g_k + (size_t)b * MIDC * N_SP;  // [m][n]
        #pragma unroll
        for (int fm = 0; fm < 4; fm++) {
            #pragma unroll
            for (int fn = 0; fn < 4; fn++) {
                int m   = wm * 64 + fm * 16 + g;
                int col = n0 + wn * 32 + fn * 8 + tig * 2;
                *(float2*)(kp + (size_t)m * N_SP + col)       = make_float2(acc[fm][fn][0], acc[fm][fn][1]);
                *(float2*)(kp + (size_t)(m + 8) * N_SP + col) = make_float2(acc[fm][fn][2], acc[fm][fn][3]);
            }
        }
    }
}

// ============================================================================
// K2a: logits L[b][i][j] = sum_m q[b][i][m] * k[b][m][j]. 3xTF32, K=128.
// ============================================================================
__global__ __launch_bounds__(256, 2) void k2_logits()
{
    const int jblk = blockIdx.x;   // 0..8
    const int iblk = blockIdx.y;   // 0..8
    const int b    = blockIdx.z;
    const float* A = g_q + (size_t)b * N_SP * MIDC;    // [1152][128]
    const float* B = g_k + (size_t)b * MIDC * N_SP;    // [128][1152]
    float* L = g_attn + (size_t)b * N_SP * N_SP;

    extern __shared__ float smem[];
    float (*As)[128][20] = (float(*)[128][20])smem;
    float (*Bs)[16][132] = (float(*)[16][132])(smem + NSTAGE * AS_ELEMS);

    const int tid  = threadIdx.x;
    const int warp = tid >> 5, lane = tid & 31;
    const int wm = warp >> 2, wn = warp & 3;
    const int g = lane >> 2, tig = lane & 3;
    const int i0 = iblk * 128, j0 = jblk * 128;

    float acc[4][4][4] = {};

    auto loadStage = [&](int kt, int buf) {
        const int k0 = kt * 16;
        #pragma unroll
        for (int it = 0; it < 2; it++) {
            int id  = tid + it * 256;
            int row = id >> 2;
            int c4  = (id & 3) * 4;
            cp_async16(&As[buf][row][c4], A + (size_t)(i0 + row) * MIDC + k0 + c4);
        }
        #pragma unroll
        for (int it = 0; it < 2; it++) {
            int id  = tid + it * 256;
            int row = id >> 5;
            int c4  = (id & 31) * 4;
            cp_async16(&Bs[buf][row][c4], B + (size_t)(k0 + row) * N_SP + j0 + c4);
        }
    };

    const int KT = MIDC / 16;   // 8
    loadStage(0, 0); cp_commit();
    loadStage(1, 1); cp_commit();

    for (int kt = 0; kt < KT; kt++) {
        if (kt + 1 < KT) cp_wait<1>(); else cp_wait<0>();
        __syncthreads();
        const int buf = kt % 3;
        if (kt + 2 < KT) { loadStage(kt + 2, (kt + 2) % 3); cp_commit(); }

        #pragma unroll
        for (int ks = 0; ks < 2; ks++) {
            const int kb = ks * 8;
            uint32_t bhi[4][2], blo[4][2];
            #pragma unroll
            for (int fn = 0; fn < 4; fn++) {
                int jc = wn * 32 + fn * 8;
                split_tf32(Bs[buf][kb + tig    ][jc + g], bhi[fn][0], blo[fn][0]);
                split_tf32(Bs[buf][kb + tig + 4][jc + g], bhi[fn][1], blo[fn][1]);
            }
            #pragma unroll
            for (int fm = 0; fm < 4; fm++) {
                int mr = wm * 64 + fm * 16;
                uint32_t ahi[4], alo[4];
                split_tf32(As[buf][mr + g    ][kb + tig    ], ahi[0], alo[0]);
                split_tf32(As[buf][mr + g + 8][kb + tig    ], ahi[1], alo[1]);
                split_tf32(As[buf][mr + g    ][kb + tig + 4], ahi[2], alo[2]);
                split_tf32(As[buf][mr + g + 8][kb + tig + 4], ahi[3], alo[3]);
                #pragma unroll
                for (int fn = 0; fn < 4; fn++) {
                    mma_tf32(acc[fm][fn], ahi, bhi[fn]);
                    mma_tf32(acc[fm][fn], alo, bhi[fn]);
                    mma_tf32(acc[fm][fn], ahi, blo[fn]);
                }
            }
        }
    }

    #pragma unroll
    for (int fm = 0; fm < 4; fm++) {
        #pragma unroll
        for (int fn = 0; fn < 4; fn++) {
            int ii  = i0 + wm * 64 + fm * 16 + g;
            int col = j0 + wn * 32 + fn * 8 + tig * 2;
            *(float2*)(L + (size_t)ii * N_SP + col)       = make_float2(acc[fm][fn][0], acc[fm][fn][1]);
            *(float2*)(L + (size_t)(ii + 8) * N_SP + col) = make_float2(acc[fm][fn][2], acc[fm][fn][3]);
        }
    }
}

// ============================================================================
// K2b: row softmax (length 1152), one warp per row. Output tf32-rounded (RNA)
// so K3's B operand is exact tf32.
// ============================================================================
__global__ void k2_softmax()
{
    const int row  = blockIdx.x * 8 + (threadIdx.x >> 5);
    const int lane = threadIdx.x & 31;
    float* r = g_attn + (size_t)row * N_SP;

    float f[36];
    float mx = -1e30f;
    #pragma unroll
    for (int t = 0; t < 36; t++) {
        f[t] = r[lane + 32 * t];
        mx = fmaxf(mx, f[t]);
    }
    #pragma unroll
    for (int o = 16; o > 0; o >>= 1) mx = fmaxf(mx, __shfl_xor_sync(0xffffffffu, mx, o));

    float s = 0.0f;
    #pragma unroll
    for (int t = 0; t < 36; t++) {
        f[t] = __expf(f[t] - mx);
        s += f[t];
    }
    #pragma unroll
    for (int o = 16; o > 0; o >>= 1) s += __shfl_xor_sync(0xffffffffu, s, o);

    const float inv = 1.0f / s;
    #pragma unroll
    for (int t = 0; t < 36; t++)
        r[lane + 32 * t] = __uint_as_float(f32_to_tf32(f[t] * inv));
}

// ============================================================================
// K3: refined = cam[b] @ attn[b]; out = alpha*refined + cam.
// TF32 mma.sync, block tile 128x128, 4 warps (2x2) of 64x64, BK=16, 3-stage
// cp.async. A operand fed raw f32 (HW truncates to tf32); B pre-rounded RNA.
// ============================================================================
__global__ __launch_bounds__(128) void k3_refined(
    const float* __restrict__ cam,
    const float* __restrict__ alphaPtr,
    float* __restrict__ out)
{
    const int jblk = blockIdx.x;   // 0..8
    const int cblk = blockIdx.y;   // 0..15
    const int b    = blockIdx.z;

    const float* A  = cam    + (size_t)b * C_CH * N_SP;   // [2048][1152]
    const float* Bm = g_attn + (size_t)b * N_SP * N_SP;   // [1152][1152] tf32-rounded

    extern __shared__ float smem[];
    float (*As)[128][20] = (float(*)[128][20])smem;
    float (*Bs)[16][136] = (float(*)[16][136])(smem + NSTAGE * AS_ELEMS);

    const int tid  = threadIdx.x;
    const int warp = tid >> 5, lane = tid & 31;
    const int wm = warp >> 1, wn = warp & 1;   // 2 x 2 warps, 64x64 each
    const int g = lane >> 2, tig = lane & 3;
    const int c0 = cblk * 128, j0 = jblk * 128;

    float acc[4][8][4] = {};

    auto loadStage = [&](int kt, int buf) {
        const int k0 = kt * 16;
        #pragma unroll
        for (int it = 0; it < 4; it++) {              // A: 128x16 = 512 float4
            int id  = tid + it * 128;
            int row = id >> 2;
            int c4  = (id & 3) * 4;
            cp_async16(&As[buf][row][c4], A + (size_t)(c0 + row) * N_SP + k0 + c4);
        }
        #pragma unroll
        for (int it = 0; it < 4; it++) {              // B: 16x128 = 512 float4
            int id  = tid + it * 128;
            int row = id >> 5;
            int c4  = (id & 31) * 4;
            cp_async16(&Bs[buf][row][c4], Bm + (size_t)(k0 + row) * N_SP + j0 + c4);
        }
    };

    const int KT = N_SP / 16;   // 72
    loadStage(0, 0); cp_commit();
    loadStage(1, 1); cp_commit();

    for (int kt = 0; kt < KT; kt++) {
        if (kt + 1 < KT) cp_wait<1>(); else cp_wait<0>();
        __syncthreads();
        const int buf = kt % 3;
        if (kt + 2 < KT) { loadStage(kt + 2, (kt + 2) % 3); cp_commit(); }

        #pragma unroll
        for (int ks = 0; ks < 2; ks++) {
            const int kb = ks * 8;
            uint32_t bfr[8][2];
            #pragma unroll
            for (int fn = 0; fn < 8; fn++) {
                int jc = wn * 64 + fn * 8;
                bfr[fn][0] = __float_as_uint(Bs[buf][kb + tig    ][jc + g]);
                bfr[fn][1] = __float_as_uint(Bs[buf][kb + tig + 4][jc + g]);
            }
            #pragma unroll
            for (int fm = 0; fm < 4; fm++) {
                int mr = wm * 64 + fm * 16;
                uint32_t afr[4];
                // raw f32 bits: HMMA truncates mantissa to tf32 internally
                afr[0] = __float_as_uint(As[buf][mr + g    ][kb + tig    ]);
                afr[1] = __float_as_uint(As[buf][mr + g + 8][kb + tig    ]);
                afr[2] = __float_as_uint(As[buf][mr + g    ][kb + tig + 4]);
                afr[3] = __float_as_uint(As[buf][mr + g + 8][kb + tig + 4]);
                #pragma unroll
                for (int fn = 0; fn < 8; fn++)
                    mma_tf32(acc[fm][fn], afr, bfr[fn]);
            }
        }
    }

    const float alpha = alphaPtr[0];
    const size_t base = (size_t)b * C_CH * N_SP;
    #pragma unroll
    for (int fm = 0; fm < 4; fm++) {
        #pragma unroll
        for (int fn = 0; fn < 8; fn++) {
            int mrow = c0 + wm * 64 + fm * 16 + g;
            int col  = j0 + wn * 64 + fn * 8 + tig * 2;
            const float2 cv0 = *(const float2*)(A + (size_t)mrow * N_SP + col);
            const float2 cv1 = *(const float2*)(A + (size_t)(mrow + 8) * N_SP + col);
            float2 r0, r1;
            r0.x = fmaf(alpha, acc[fm][fn][0], cv0.x);
            r0.y = fmaf(alpha, acc[fm][fn][1], cv0.y);
            r1.x = fmaf(alpha, acc[fm][fn][2], cv1.x);
            r1.y = fmaf(alpha, acc[fm][fn][3], cv1.y);
            *(float2*)(out + base + (size_t)mrow * N_SP + col)       = r0;
            *(float2*)(out + base + (size_t)(mrow + 8) * N_SP + col) = r1;
        }
    }
}

// ============================================================================
extern "C" void kernel_launch(void* const* d_in, const int* in_sizes, int n_in,
                              void* d_out, int out_size)
{
    (void)in_sizes; (void)n_in; (void)out_size;
    const float* feat  = (const float*)d_in[0];
    const float* cam   = (const float*)d_in[1];
    const float* Wq    = (const float*)d_in[2];
    const float* Wk    = (const float*)d_in[3];
    const float* alpha = (const float*)d_in[4];
    float* out = (float*)d_out;

    cudaFuncSetAttribute(k1_proj,    cudaFuncAttributeMaxDynamicSharedMemorySize, K1_SMEM);
    cudaFuncSetAttribute(k2_logits,  cudaFuncAttributeMaxDynamicSharedMemorySize, K2_SMEM);
    cudaFuncSetAttribute(k3_refined, cudaFuncAttributeMaxDynamicSharedMemorySize, K3_SMEM);

    k0_splitW<<<(MIDC * C_CH + 255) / 256, 256>>>(Wq, Wk);
    k1_proj<<<dim3(9, 2, BATCH), 256, K1_SMEM>>>(feat);
    k2_logits<<<dim3(9, 9, BATCH), 256, K2_SMEM>>>();
    k2_softmax<<<(BATCH * N_SP) / 8, 256>>>();
    k3_refined<<<dim3(9, 16, BATCH), 128, K3_SMEM>>>(cam, alpha, out);
}